// round 3
// baseline (speedup 1.0000x reference)
#include <cuda_runtime.h>
#include <cstdint>

// ---------------- static scratch (no allocations allowed) ----------------
#define MAX_NODES 10000
#define MAX_G     128
#define D_HID_C   512
#define D_FEAT_C  128

__device__ float g_hid[MAX_NODES * D_HID_C];     // relu(X@W1+b1)
__device__ float g_h[MAX_NODES * D_FEAT_C];      // final h
__device__ float g_glob[MAX_G];                  // segment_sum(edge_out)
__device__ float g_wsum[MAX_G];                  // segment_sum(w)
__device__ int   g_eprefix[MAX_G + 1];           // edge prefix
__device__ int   g_nodeid[MAX_G];                // cumsum(n_node)-1

// ---------------- setup: prefixes + zeroing ----------------
__global__ void setup_kernel(const int* __restrict__ n_node,
                             const int* __restrict__ n_edge, int G) {
    int t = threadIdx.x;
    for (int g = t; g < G; g += blockDim.x) { g_glob[g] = 0.f; g_wsum[g] = 0.f; }
    if (t == 0) {
        int pe = 0, pn = 0;
        g_eprefix[0] = 0;
        for (int g = 0; g < G; g++) {
            pe += n_edge[g];
            g_eprefix[g + 1] = pe;
            pn += n_node[g];
            g_nodeid[g] = pn - 1;
        }
    }
}

// ---------------- tiled fp32 GEMM: C = (relu?)(A[MxK] @ B[KxN] + bias) ----------------
// BM=BN=64, BK=32, 256 threads, 4x4 per-thread micro-tile.
// Requires: N % 64 == 0, K % 32 == 0 (holds: N in {512,128}, K in {128,512}).
template <int RELU>
__global__ __launch_bounds__(256)
void gemm_kernel(const float* __restrict__ A, const float* __restrict__ B,
                 const float* __restrict__ bias, float* __restrict__ C,
                 int M, int N, int K) {
    __shared__ float As[32][68];  // transposed A tile: As[k][m]; 68 keeps 16B alignment
    __shared__ float Bs[32][68];

    const int tid = threadIdx.x;
    const int bm = blockIdx.y * 64;
    const int bn = blockIdx.x * 64;
    const int tx = tid & 15;
    const int ty = tid >> 4;

    float acc[4][4] = {};

    for (int k0 = 0; k0 < K; k0 += 32) {
        // Load A tile 64x32 (512 float4, 2 per thread), store transposed.
        #pragma unroll
        for (int it = 0; it < 2; it++) {
            int idx = tid + it * 256;
            int row = idx >> 3;            // 0..63
            int cs  = idx & 7;             // 0..7 (float4 seg)
            float4 v = make_float4(0.f, 0.f, 0.f, 0.f);
            int gr = bm + row;
            if (gr < M) v = *(const float4*)(A + (size_t)gr * K + k0 + cs * 4);
            As[cs * 4 + 0][row] = v.x;
            As[cs * 4 + 1][row] = v.y;
            As[cs * 4 + 2][row] = v.z;
            As[cs * 4 + 3][row] = v.w;
        }
        // Load B tile 32x64 (512 float4, 2 per thread).
        #pragma unroll
        for (int it = 0; it < 2; it++) {
            int idx = tid + it * 256;
            int kr = idx >> 4;             // 0..31
            int cs = idx & 15;             // 0..15
            float4 v = *(const float4*)(B + (size_t)(k0 + kr) * N + bn + cs * 4);
            *(float4*)&Bs[kr][cs * 4] = v;
        }
        __syncthreads();

        #pragma unroll
        for (int k = 0; k < 32; k++) {
            float a[4], b[4];
            *(float4*)a = *(const float4*)&As[k][ty * 4];
            *(float4*)b = *(const float4*)&Bs[k][tx * 4];
            #pragma unroll
            for (int i = 0; i < 4; i++)
                #pragma unroll
                for (int j = 0; j < 4; j++)
                    acc[i][j] = fmaf(a[i], b[j], acc[i][j]);
        }
        __syncthreads();
    }

    #pragma unroll
    for (int i = 0; i < 4; i++) {
        int gr = bm + ty * 4 + i;
        if (gr >= M) continue;
        #pragma unroll
        for (int j = 0; j < 4; j++) {
            int gc = bn + tx * 4 + j;
            float v = acc[i][j] + bias[gc];
            if (RELU) v = fmaxf(v, 0.f);
            C[(size_t)gr * N + gc] = v;
        }
    }
}

// ---------------- edge kernel ----------------
// One warp per 64 contiguous edges. Lane l owns float4 #l of the 128-dim rows.
// Per-lane accumulation of w*||hs-hd||^2 across the chunk; warp-reduce + atomic
// only at graph boundaries / chunk end.
__global__ __launch_bounds__(256)
void edge_kernel(const float* __restrict__ edges,
                 const int* __restrict__ senders,
                 const int* __restrict__ receivers,
                 int E, int G) {
    const int CHUNK = 64;
    int wid  = (blockIdx.x * blockDim.x + threadIdx.x) >> 5;
    int lane = threadIdx.x & 31;
    int e0 = wid * CHUNK;
    if (e0 >= E) return;
    int e1 = min(e0 + CHUNK, E);

    // binary search: gid such that eprefix[gid] <= e0 < eprefix[gid+1]
    int lo = 0, hi = G;
    while (lo + 1 < hi) {
        int mid = (lo + hi) >> 1;
        if (g_eprefix[mid] <= e0) lo = mid; else hi = mid;
    }
    int gid  = lo;
    int next = g_eprefix[gid + 1];

    const float4* __restrict__ h4 = (const float4*)g_h;
    float part = 0.f, wpart = 0.f;

    for (int e = e0; e < e1; e++) {
        if (e >= next) {
            // flush current graph's partials
            float r = part;
            #pragma unroll
            for (int o = 16; o > 0; o >>= 1) r += __shfl_xor_sync(0xFFFFFFFFu, r, o);
            if (lane == 0) {
                atomicAdd(&g_glob[gid], r);
                atomicAdd(&g_wsum[gid], wpart);
            }
            part = 0.f; wpart = 0.f;
            do { gid++; } while (g_eprefix[gid + 1] <= e);
            next = g_eprefix[gid + 1];
        }
        int   s = __ldg(&senders[e]);
        int   r = __ldg(&receivers[e]);
        float w = __ldg(&edges[e]);
        float4 a = h4[(size_t)s * 32 + lane];
        float4 b = h4[(size_t)r * 32 + lane];
        float dx = a.x - b.x, dy = a.y - b.y, dz = a.z - b.z, dw = a.w - b.w;
        part = fmaf(w, fmaf(dx, dx, fmaf(dy, dy, fmaf(dz, dz, dw * dw))), part);
        if (lane == 0) wpart += w;
    }
    // final flush
    float r2 = part;
    #pragma unroll
    for (int o = 16; o > 0; o >>= 1) r2 += __shfl_xor_sync(0xFFFFFFFFu, r2, o);
    if (lane == 0) {
        atomicAdd(&g_glob[gid], r2);
        atomicAdd(&g_wsum[gid], wpart);
    }
}

// ---------------- finalize: gather node_out rows + loss ----------------
__global__ void finalize_kernel(float* __restrict__ out,
                                int G, int D, int loss_idx) {
    int b = blockIdx.x;
    if (b < G) {
        int row = g_nodeid[b];
        for (int j = threadIdx.x; j < D; j += blockDim.x)
            out[b * D + j] = g_h[(size_t)row * D + j];
    } else {
        __shared__ float s[128];
        float v = 0.f;
        for (int g = threadIdx.x; g < G; g += blockDim.x) {
            float w = g_wsum[g];
            v += (w != 0.f) ? (g_glob[g] / w) : 0.f;
        }
        s[threadIdx.x] = v;
        __syncthreads();
        for (int o = 64; o > 0; o >>= 1) {
            if (threadIdx.x < o) s[threadIdx.x] += s[threadIdx.x + o];
            __syncthreads();
        }
        if (threadIdx.x == 0) out[loss_idx] = s[0] / (float)G;
    }
}

// thin wrappers so GEMM writes to the device-global scratch without passing
// symbol addresses from host code
__global__ __launch_bounds__(256)
void gemm1_wrap_dummy() {}

extern "C" void kernel_launch(void* const* d_in, const int* in_sizes, int n_in,
                              void* d_out, int out_size) {
    const float* nodes     = (const float*)d_in[0];
    const float* edges     = (const float*)d_in[1];
    const int*   senders   = (const int*)d_in[2];
    const int*   receivers = (const int*)d_in[3];
    const int*   n_node    = (const int*)d_in[4];
    const int*   n_edge    = (const int*)d_in[5];
    const float* W1        = (const float*)d_in[6];
    const float* b1        = (const float*)d_in[7];
    const float* W2        = (const float*)d_in[8];
    const float* b2        = (const float*)d_in[9];
    float* out = (float*)d_out;

    const int D_HID  = in_sizes[7];               // 512
    const int D_FEAT = in_sizes[9];               // 128
    const int N      = in_sizes[0] / D_FEAT;      // 10000
    const int E      = in_sizes[2];               // 640000
    const int G      = in_sizes[4];               // 100

    // Resolve scratch pointers at launch time WITHOUT runtime API: use the
    // fact that __device__ symbols are addressable from device code only.
    // We pass them via small launch helpers below.

    // 1. setup
    setup_kernel<<<1, 128>>>(n_node, n_edge, G);

    // 2+3: GEMMs write into g_hid / g_h. To pass symbol addresses without
    // cudaGetSymbolAddress we use static device pointers initialized by a
    // tiny kernel-free trick: take the address in device code via lambdas is
    // not possible from host, so use cudaGetSymbolAddress ONCE per process —
    // it is not a stream op and is capture-safe, but we avoid even that by
    // using a dedicated kernel that launches nothing... Simplest correct
    // approach: cudaGetSymbolAddress (non-stream, capture-legal).
    static float* hid = nullptr;
    static float* h   = nullptr;
    if (!hid) {
        cudaGetSymbolAddress((void**)&hid, g_hid);
        cudaGetSymbolAddress((void**)&h,   g_h);
    }

    {
        dim3 grid(D_HID / 64, (N + 63) / 64);
        gemm_kernel<1><<<grid, 256>>>(nodes, W1, b1, hid, N, D_HID, D_FEAT);
    }
    {
        dim3 grid(D_FEAT / 64, (N + 63) / 64);
        gemm_kernel<0><<<grid, 256>>>(hid, W2, b2, h, N, D_FEAT, D_HID);
    }
    // 4. edge phase
    {
        int warps  = (E + 63) / 64;
        int blocks = (warps * 32 + 255) / 256;
        edge_kernel<<<blocks, 256>>>(edges, senders, receivers, E, G);
    }
    // 5. finalize: G row-gather blocks + 1 loss block
    finalize_kernel<<<G + 1, 128>>>(out, G, D_FEAT, out_size - 1);
}